// round 10
// baseline (speedup 1.0000x reference)
#include <cuda_runtime.h>
#include <cuda_fp16.h>
#include <cstdint>

#define IN_F   4096
#define OUT_F  11008
#define M_TOT  8192

#define BM 128
#define BN 128
#define BK 64
#define NSTAGE 3
#define KT_CNT (IN_F / BK)   // 64
#define ASTR 72              // row stride in halves (128B data + 16B pad)

__device__ __align__(16) __half g_W[(size_t)OUT_F * IN_F];
__device__ __align__(16) __half g_X[(size_t)M_TOT * IN_F];

static __device__ __forceinline__ uint32_t smem_u32(const void* p) {
    return (uint32_t)__cvta_generic_to_shared(p);
}
static __device__ __forceinline__ void cp16(uint32_t dst, const void* src) {
    asm volatile("cp.async.cg.shared.global [%0], [%1], 16;\n" :: "r"(dst), "l"(src));
}
static __device__ __forceinline__ void ldsm4(uint32_t* d, uint32_t addr) {
    asm volatile("ldmatrix.sync.aligned.m8n8.x4.shared.b16 {%0,%1,%2,%3}, [%4];"
        : "=r"(d[0]), "=r"(d[1]), "=r"(d[2]), "=r"(d[3]) : "r"(addr));
}

// ---------------------------------------------------------------------------
// Fused prep: blocks [0, XBLK) do xscale, blocks [XBLK, XBLK+QBLK) do dequant.
// ---------------------------------------------------------------------------
#define XBLK ((M_TOT * IN_F / 8) / 256)              // 16384
#define QBLK ((OUT_F * (IN_F / 2) / 4) / 256)        // 5504

__global__ __launch_bounds__(256)
void prep_kernel(const float* __restrict__ x, const float* __restrict__ iscale,
                 const int* __restrict__ qw, const float* __restrict__ scales,
                 const float* __restrict__ zeros) {
    if (blockIdx.x < XBLK) {
        int idx = blockIdx.x * 256 + threadIdx.x;
        const float4* xp = (const float4*)x;
        float4 a = xp[2 * idx], b = xp[2 * idx + 1];
        int k4 = (2 * idx) & 1023;
        float4 sa = ((const float4*)iscale)[k4];
        float4 sb = ((const float4*)iscale)[k4 + 1];
        uint4 r;
        __half2 h;
        h = __floats2half2_rn(a.x * sa.x, a.y * sa.y); r.x = *reinterpret_cast<uint32_t*>(&h);
        h = __floats2half2_rn(a.z * sa.z, a.w * sa.w); r.y = *reinterpret_cast<uint32_t*>(&h);
        h = __floats2half2_rn(b.x * sb.x, b.y * sb.y); r.z = *reinterpret_cast<uint32_t*>(&h);
        h = __floats2half2_rn(b.z * sb.z, b.w * sb.w); r.w = *reinterpret_cast<uint32_t*>(&h);
        ((uint4*)g_X)[idx] = r;
    } else {
        int idx = (blockIdx.x - XBLK) * 256 + threadIdx.x;
        int4 v = ((const int4*)qw)[idx];
        int o  = idx >> 9;
        int jq = idx & 511;
        int g  = jq >> 4;
        float s  = scales[o * 32 + g];
        float zs = -zeros[o * 32 + g] * s;
        uint4 outv;
        __half2 h;
        h = __floats2half2_rn((float)((v.x >> 4) & 15) * s + zs, (float)(v.x & 15) * s + zs);
        outv.x = *reinterpret_cast<uint32_t*>(&h);
        h = __floats2half2_rn((float)((v.y >> 4) & 15) * s + zs, (float)(v.y & 15) * s + zs);
        outv.y = *reinterpret_cast<uint32_t*>(&h);
        h = __floats2half2_rn((float)((v.z >> 4) & 15) * s + zs, (float)(v.z & 15) * s + zs);
        outv.z = *reinterpret_cast<uint32_t*>(&h);
        h = __floats2half2_rn((float)((v.w >> 4) & 15) * s + zs, (float)(v.w & 15) * s + zs);
        outv.w = *reinterpret_cast<uint32_t*>(&h);
        ((uint4*)g_W)[(size_t)o * 512 + jq] = outv;
    }
}

// ---------------------------------------------------------------------------
// GEMM: BM=BN=128, 4 warps (2x2), 64x64 warp tile, BK=64, 3-stage cp.async,
// 2 CTAs/SM. Barriers every 64 K (half as many as BK=32) amortize the fixed
// wait+sync+LDSM-warmup overhead over 2x the MMA work.
// ---------------------------------------------------------------------------
__global__ __launch_bounds__(128, 2)
void gemm_kernel(const float* __restrict__ bias, float* __restrict__ C) {
    extern __shared__ __half smem[];
    __half* smA = smem;                         // NSTAGE * BM * ASTR
    __half* smB = smem + NSTAGE * BM * ASTR;    // NSTAGE * BN * ASTR

    const int tid  = threadIdx.x;
    const int lane = tid & 31;
    const int wid  = tid >> 5;
    const int wm   = wid & 1;    // 2 warp rows of 64
    const int wn   = wid >> 1;   // 2 warp cols of 64
    const int m0   = blockIdx.y * BM;
    const int n0   = blockIdx.x * BN;

    const char* gA = (const char*)(g_X + (size_t)m0 * IN_F);
    const char* gB = (const char*)(g_W + (size_t)n0 * IN_F);

    float acc[4][8][4];
    #pragma unroll
    for (int i = 0; i < 4; i++)
        #pragma unroll
        for (int j = 0; j < 8; j++)
            #pragma unroll
            for (int k = 0; k < 4; k++) acc[i][j][k] = 0.f;

    // lane-constant smem read offsets (bytes within a stage); kk adds 32B each
    uint32_t aoffs[4], boffs[4];
    #pragma unroll
    for (int mt = 0; mt < 4; mt++) {
        int row = wm * 64 + mt * 16 + (lane & 15);
        int col = (lane >> 4) * 8;
        aoffs[mt] = (uint32_t)(row * ASTR + col) * 2;
    }
    {
        int mi = lane >> 3, r = lane & 7;
        #pragma unroll
        for (int ntp = 0; ntp < 4; ntp++) {
            int n = wn * 64 + ntp * 16 + (mi >> 1) * 8 + r;
            int k = (mi & 1) * 8;
            boffs[ntp] = (uint32_t)(n * ASTR + k) * 2;
        }
    }

    // loader: per stage A=1024 chunks, B=1024 chunks over 128 threads (8+8 each)
    const int rA = tid >> 3, cA = tid & 7;
    auto issue = [&](int kt, int slot) {
        __half* sA = smA + slot * (BM * ASTR);
        __half* sB = smB + slot * (BN * ASTR);
        size_t koff = (size_t)kt * (BK * 2);   // byte offset in K
        #pragma unroll
        for (int i = 0; i < 8; i++) {
            int r = rA + i * 16;
            cp16(smem_u32(sA + r * ASTR + cA * 8),
                 gA + (size_t)r * (IN_F * 2) + koff + cA * 16);
            cp16(smem_u32(sB + r * ASTR + cA * 8),
                 gB + (size_t)r * (IN_F * 2) + koff + cA * 16);
        }
        asm volatile("cp.async.commit_group;\n");
    };

    uint32_t abuf[2][4][4];   // [buf][mt][frag]
    uint32_t bbuf[2][8][2];   // [buf][nt][frag]

    auto loadA = [&](uint32_t (*ab)[4], uint32_t base, uint32_t kkoff) {
        #pragma unroll
        for (int mt = 0; mt < 4; mt++) ldsm4(ab[mt], base + aoffs[mt] + kkoff);
    };
    auto loadB = [&](uint32_t (*bb)[2], uint32_t base, uint32_t kkoff) {
        #pragma unroll
        for (int ntp = 0; ntp < 4; ntp++) {
            uint32_t t[4];
            ldsm4(t, base + boffs[ntp] + kkoff);
            bb[2 * ntp][0] = t[0]; bb[2 * ntp][1] = t[1];
            bb[2 * ntp + 1][0] = t[2]; bb[2 * ntp + 1][1] = t[3];
        }
    };
    auto domma = [&](uint32_t (*ab)[4], uint32_t (*bb)[2]) {
        #pragma unroll
        for (int mt = 0; mt < 4; mt++)
            #pragma unroll
            for (int nt = 0; nt < 8; nt++) {
                asm volatile(
                    "mma.sync.aligned.m16n8k16.row.col.f32.f16.f16.f32 "
                    "{%0,%1,%2,%3}, {%4,%5,%6,%7}, {%8,%9}, {%0,%1,%2,%3};"
                    : "+f"(acc[mt][nt][0]), "+f"(acc[mt][nt][1]),
                      "+f"(acc[mt][nt][2]), "+f"(acc[mt][nt][3])
                    : "r"(ab[mt][0]), "r"(ab[mt][1]), "r"(ab[mt][2]), "r"(ab[mt][3]),
                      "r"(bb[nt][0]), "r"(bb[nt][1]));
            }
    };

    issue(0, 0); issue(1, 1);

    int cslot = 0;   // slot being consumed
    int islot = 2;   // slot to fill this iteration (kt+2)
    for (int kt = 0; kt < KT_CNT; kt++) {
        asm volatile("cp.async.wait_group 1;\n");   // slot kt complete
        __syncthreads();                            // CTA-wide visibility; slot islot free

        uint32_t ca = smem_u32(smA + cslot * (BM * ASTR));
        uint32_t cb = smem_u32(smB + cslot * (BN * ASTR));

        // kk0 into buf0
        loadA(abuf[0], ca, 0);
        loadB(bbuf[0], cb, 0);

        if (kt + 2 < KT_CNT) issue(kt + 2, islot);
        else asm volatile("cp.async.commit_group;\n");

        // kk pipeline: load kk+1 while MMA kk
        loadA(abuf[1], ca, 32);
        loadB(bbuf[1], cb, 32);
        domma(abuf[0], bbuf[0]);           // kk0

        loadA(abuf[0], ca, 64);
        loadB(bbuf[0], cb, 64);
        domma(abuf[1], bbuf[1]);           // kk1

        loadA(abuf[1], ca, 96);
        loadB(bbuf[1], cb, 96);
        domma(abuf[0], bbuf[0]);           // kk2

        domma(abuf[1], bbuf[1]);           // kk3

        cslot = (cslot + 1 == NSTAGE) ? 0 : cslot + 1;
        islot = (islot + 1 == NSTAGE) ? 0 : islot + 1;
    }

    #pragma unroll
    for (int mt = 0; mt < 4; mt++) {
        int row = m0 + wm * 64 + mt * 16 + (lane >> 2);
        #pragma unroll
        for (int nt = 0; nt < 8; nt++) {
            int col = n0 + wn * 64 + nt * 8 + (lane & 3) * 2;
            float2 bv = *reinterpret_cast<const float2*>(bias + col);
            float2 v0 = make_float2(acc[mt][nt][0] + bv.x, acc[mt][nt][1] + bv.y);
            float2 v1 = make_float2(acc[mt][nt][2] + bv.x, acc[mt][nt][3] + bv.y);
            *reinterpret_cast<float2*>(C + (size_t)row * OUT_F + col)       = v0;
            *reinterpret_cast<float2*>(C + (size_t)(row + 8) * OUT_F + col) = v1;
        }
    }
}

// ---------------------------------------------------------------------------
extern "C" void kernel_launch(void* const* d_in, const int* in_sizes, int n_in,
                              void* d_out, int out_size) {
    const float* x      = (const float*)d_in[0];
    const int*   qw     = (const int*)  d_in[1];
    const float* scales = (const float*)d_in[2];
    const float* zeros  = (const float*)d_in[3];
    const float* iscale = (const float*)d_in[4];
    const float* bias   = (const float*)d_in[5];
    float* out = (float*)d_out;

    prep_kernel<<<XBLK + QBLK, 256>>>(x, iscale, qw, scales, zeros);

    constexpr int SMEM_BYTES = NSTAGE * (BM + BN) * ASTR * 2;   // 110592
    cudaFuncSetAttribute(gemm_kernel, cudaFuncAttributeMaxDynamicSharedMemorySize, SMEM_BYTES);
    dim3 grid(OUT_F / BN, M_TOT / BM);   // 86 x 64
    gemm_kernel<<<grid, 128, SMEM_BYTES>>>(bias, out);
}

// round 11
// speedup vs baseline: 1.1083x; 1.1083x over previous
#include <cuda_runtime.h>
#include <cuda_fp16.h>
#include <cstdint>

#define IN_F   4096
#define OUT_F  11008
#define M_TOT  8192

#define BM 128
#define BN 128
#define BK 64
#define NSTAGE 3
#define KT_CNT (IN_F / BK)   // 64
#define ASTR 72              // row stride in halves (128B data + 16B pad)

__device__ __align__(16) __half g_W[(size_t)OUT_F * IN_F];
__device__ __align__(16) __half g_X[(size_t)M_TOT * IN_F];

static __device__ __forceinline__ uint32_t smem_u32(const void* p) {
    return (uint32_t)__cvta_generic_to_shared(p);
}
static __device__ __forceinline__ void cp16(uint32_t dst, const void* src) {
    asm volatile("cp.async.cg.shared.global [%0], [%1], 16;\n" :: "r"(dst), "l"(src));
}
static __device__ __forceinline__ void ldsm4(uint32_t* d, uint32_t addr) {
    asm volatile("ldmatrix.sync.aligned.m8n8.x4.shared.b16 {%0,%1,%2,%3}, [%4];"
        : "=r"(d[0]), "=r"(d[1]), "=r"(d[2]), "=r"(d[3]) : "r"(addr));
}

// ---------------------------------------------------------------------------
// Fused prep: blocks [0, XBLK) do xscale, blocks [XBLK, XBLK+QBLK) do dequant.
// ---------------------------------------------------------------------------
#define XBLK ((M_TOT * IN_F / 8) / 256)              // 16384
#define QBLK ((OUT_F * (IN_F / 2) / 4) / 256)        // 5504

__global__ __launch_bounds__(256)
void prep_kernel(const float* __restrict__ x, const float* __restrict__ iscale,
                 const int* __restrict__ qw, const float* __restrict__ scales,
                 const float* __restrict__ zeros) {
    if (blockIdx.x < XBLK) {
        int idx = blockIdx.x * 256 + threadIdx.x;
        const float4* xp = (const float4*)x;
        float4 a = xp[2 * idx], b = xp[2 * idx + 1];
        int k4 = (2 * idx) & 1023;
        float4 sa = ((const float4*)iscale)[k4];
        float4 sb = ((const float4*)iscale)[k4 + 1];
        uint4 r;
        __half2 h;
        h = __floats2half2_rn(a.x * sa.x, a.y * sa.y); r.x = *reinterpret_cast<uint32_t*>(&h);
        h = __floats2half2_rn(a.z * sa.z, a.w * sa.w); r.y = *reinterpret_cast<uint32_t*>(&h);
        h = __floats2half2_rn(b.x * sb.x, b.y * sb.y); r.z = *reinterpret_cast<uint32_t*>(&h);
        h = __floats2half2_rn(b.z * sb.z, b.w * sb.w); r.w = *reinterpret_cast<uint32_t*>(&h);
        ((uint4*)g_X)[idx] = r;
    } else {
        int idx = (blockIdx.x - XBLK) * 256 + threadIdx.x;
        int4 v = ((const int4*)qw)[idx];
        int o  = idx >> 9;
        int jq = idx & 511;
        int g  = jq >> 4;
        float s  = scales[o * 32 + g];
        float zs = -zeros[o * 32 + g] * s;
        uint4 outv;
        __half2 h;
        h = __floats2half2_rn((float)((v.x >> 4) & 15) * s + zs, (float)(v.x & 15) * s + zs);
        outv.x = *reinterpret_cast<uint32_t*>(&h);
        h = __floats2half2_rn((float)((v.y >> 4) & 15) * s + zs, (float)(v.y & 15) * s + zs);
        outv.y = *reinterpret_cast<uint32_t*>(&h);
        h = __floats2half2_rn((float)((v.z >> 4) & 15) * s + zs, (float)(v.z & 15) * s + zs);
        outv.z = *reinterpret_cast<uint32_t*>(&h);
        h = __floats2half2_rn((float)((v.w >> 4) & 15) * s + zs, (float)(v.w & 15) * s + zs);
        outv.w = *reinterpret_cast<uint32_t*>(&h);
        ((uint4*)g_W)[(size_t)o * 512 + jq] = outv;
    }
}

// ---------------------------------------------------------------------------
// GEMM: BM=BN=128, 4 warps (2x2), 64x64 warp tile, BK=64, 3-stage cp.async,
// 2 CTAs/SM. wait_group 0 at iteration top guarantees slots kt AND kt+1
// complete, enabling cross-tile register prefetch (zero exposed LDSM at the
// iteration head) while halving barrier frequency vs BK=32.
// ---------------------------------------------------------------------------
__global__ __launch_bounds__(128, 2)
void gemm_kernel(const float* __restrict__ bias, float* __restrict__ C) {
    extern __shared__ __half smem[];
    __half* smA = smem;                         // NSTAGE * BM * ASTR
    __half* smB = smem + NSTAGE * BM * ASTR;    // NSTAGE * BN * ASTR

    const int tid  = threadIdx.x;
    const int lane = tid & 31;
    const int wid  = tid >> 5;
    const int wm   = wid & 1;    // 2 warp rows of 64
    const int wn   = wid >> 1;   // 2 warp cols of 64
    const int m0   = blockIdx.y * BM;
    const int n0   = blockIdx.x * BN;

    const char* gA = (const char*)(g_X + (size_t)m0 * IN_F);
    const char* gB = (const char*)(g_W + (size_t)n0 * IN_F);

    float acc[4][8][4];
    #pragma unroll
    for (int i = 0; i < 4; i++)
        #pragma unroll
        for (int j = 0; j < 8; j++)
            #pragma unroll
            for (int k = 0; k < 4; k++) acc[i][j][k] = 0.f;

    // lane-constant smem read offsets (bytes within a stage); kk adds 32B each
    uint32_t aoffs[4], boffs[4];
    #pragma unroll
    for (int mt = 0; mt < 4; mt++) {
        int row = wm * 64 + mt * 16 + (lane & 15);
        int col = (lane >> 4) * 8;
        aoffs[mt] = (uint32_t)(row * ASTR + col) * 2;
    }
    {
        int mi = lane >> 3, r = lane & 7;
        #pragma unroll
        for (int ntp = 0; ntp < 4; ntp++) {
            int n = wn * 64 + ntp * 16 + (mi >> 1) * 8 + r;
            int k = (mi & 1) * 8;
            boffs[ntp] = (uint32_t)(n * ASTR + k) * 2;
        }
    }

    // loader: per stage A=1024 chunks, B=1024 chunks over 128 threads (8+8 each)
    const int rA = tid >> 3, cA = tid & 7;
    auto issue = [&](int kt, int slot) {
        __half* sA = smA + slot * (BM * ASTR);
        __half* sB = smB + slot * (BN * ASTR);
        size_t koff = (size_t)kt * (BK * 2);   // byte offset in K
        #pragma unroll
        for (int i = 0; i < 8; i++) {
            int r = rA + i * 16;
            cp16(smem_u32(sA + r * ASTR + cA * 8),
                 gA + (size_t)r * (IN_F * 2) + koff + cA * 16);
            cp16(smem_u32(sB + r * ASTR + cA * 8),
                 gB + (size_t)r * (IN_F * 2) + koff + cA * 16);
        }
        asm volatile("cp.async.commit_group;\n");
    };

    uint32_t abuf[2][4][4];   // [buf][mt][frag]
    uint32_t bbuf[2][8][2];   // [buf][nt][frag]

    auto loadA = [&](uint32_t (*ab)[4], uint32_t base, uint32_t kkoff) {
        #pragma unroll
        for (int mt = 0; mt < 4; mt++) ldsm4(ab[mt], base + aoffs[mt] + kkoff);
    };
    auto loadB = [&](uint32_t (*bb)[2], uint32_t base, uint32_t kkoff) {
        #pragma unroll
        for (int ntp = 0; ntp < 4; ntp++) {
            uint32_t t[4];
            ldsm4(t, base + boffs[ntp] + kkoff);
            bb[2 * ntp][0] = t[0]; bb[2 * ntp][1] = t[1];
            bb[2 * ntp + 1][0] = t[2]; bb[2 * ntp + 1][1] = t[3];
        }
    };
    auto domma = [&](uint32_t (*ab)[4], uint32_t (*bb)[2]) {
        #pragma unroll
        for (int mt = 0; mt < 4; mt++)
            #pragma unroll
            for (int nt = 0; nt < 8; nt++) {
                asm volatile(
                    "mma.sync.aligned.m16n8k16.row.col.f32.f16.f16.f32 "
                    "{%0,%1,%2,%3}, {%4,%5,%6,%7}, {%8,%9}, {%0,%1,%2,%3};"
                    : "+f"(acc[mt][nt][0]), "+f"(acc[mt][nt][1]),
                      "+f"(acc[mt][nt][2]), "+f"(acc[mt][nt][3])
                    : "r"(ab[mt][0]), "r"(ab[mt][1]), "r"(ab[mt][2]), "r"(ab[mt][3]),
                      "r"(bb[nt][0]), "r"(bb[nt][1]));
            }
    };

    issue(0, 0); issue(1, 1);
    asm volatile("cp.async.wait_group 0;\n");   // slots 0 and 1 complete
    __syncthreads();

    // prime buf0 with (slot 0, kk0)
    loadA(abuf[0], smem_u32(smA), 0);
    loadB(bbuf[0], smem_u32(smB), 0);

    int cslot = 0;   // slot being consumed
    int islot = 2;   // slot to fill this iteration (kt+2)
    for (int kt = 0; kt < KT_CNT; kt++) {
        // invariant: buf0 = kk0 of slot kt (regs); slots kt, kt+1 complete in smem
        uint32_t ca = smem_u32(smA + cslot * (BM * ASTR));
        uint32_t cb = smem_u32(smB + cslot * (BN * ASTR));

        // kk1 LDSM first (ahead of the cp.async burst in the LSU queue)
        loadA(abuf[1], ca, 32);
        loadB(bbuf[1], cb, 32);

        if (kt + 2 < KT_CNT) issue(kt + 2, islot);

        domma(abuf[0], bbuf[0]);           // kk0 (already in regs)

        loadA(abuf[0], ca, 64);
        loadB(bbuf[0], cb, 64);
        domma(abuf[1], bbuf[1]);           // kk1

        loadA(abuf[1], ca, 96);
        loadB(bbuf[1], cb, 96);
        domma(abuf[0], bbuf[0]);           // kk2

        // cross-tile prefetch: kk0 of slot kt+1 (complete — covered by the wait)
        if (kt + 1 < KT_CNT) {
            int ns = (cslot + 1 == NSTAGE) ? 0 : cslot + 1;
            loadA(abuf[0], smem_u32(smA + ns * (BM * ASTR)), 0);
            loadB(bbuf[0], smem_u32(smB + ns * (BN * ASTR)), 0);
        }
        domma(abuf[1], bbuf[1]);           // kk3

        // end-of-iteration barrier: group kt+2 (and all prior) must complete,
        // and all warps must be done reading slot kt before it is rewritten.
        if (kt + 1 < KT_CNT) {
            asm volatile("cp.async.wait_group 0;\n");
            __syncthreads();
        }

        cslot = (cslot + 1 == NSTAGE) ? 0 : cslot + 1;
        islot = (islot + 1 == NSTAGE) ? 0 : islot + 1;
    }

    #pragma unroll
    for (int mt = 0; mt < 4; mt++) {
        int row = m0 + wm * 64 + mt * 16 + (lane >> 2);
        #pragma unroll
        for (int nt = 0; nt < 8; nt++) {
            int col = n0 + wn * 64 + nt * 8 + (lane & 3) * 2;
            float2 bv = *reinterpret_cast<const float2*>(bias + col);
            float2 v0 = make_float2(acc[mt][nt][0] + bv.x, acc[mt][nt][1] + bv.y);
            float2 v1 = make_float2(acc[mt][nt][2] + bv.x, acc[mt][nt][3] + bv.y);
            *reinterpret_cast<float2*>(C + (size_t)row * OUT_F + col)       = v0;
            *reinterpret_cast<float2*>(C + (size_t)(row + 8) * OUT_F + col) = v1;
        }
    }
}

// ---------------------------------------------------------------------------
extern "C" void kernel_launch(void* const* d_in, const int* in_sizes, int n_in,
                              void* d_out, int out_size) {
    const float* x      = (const float*)d_in[0];
    const int*   qw     = (const int*)  d_in[1];
    const float* scales = (const float*)d_in[2];
    const float* zeros  = (const float*)d_in[3];
    const float* iscale = (const float*)d_in[4];
    const float* bias   = (const float*)d_in[5];
    float* out = (float*)d_out;

    prep_kernel<<<XBLK + QBLK, 256>>>(x, iscale, qw, scales, zeros);

    constexpr int SMEM_BYTES = NSTAGE * (BM + BN) * ASTR * 2;   // 110592
    cudaFuncSetAttribute(gemm_kernel, cudaFuncAttributeMaxDynamicSharedMemorySize, SMEM_BYTES);
    dim3 grid(OUT_F / BN, M_TOT / BM);   // 86 x 64
    gemm_kernel<<<grid, 128, SMEM_BYTES>>>(bias, out);
}

// round 12
// speedup vs baseline: 1.3076x; 1.1799x over previous
#include <cuda_runtime.h>
#include <cuda_fp16.h>
#include <cstdint>

#define IN_F   4096
#define OUT_F  11008
#define M_TOT  8192

#define BM 128
#define BN 128
#define BK 64
#define NSTAGE 3
#define KT_CNT (IN_F / BK)   // 64
#define ASTR 72              // row stride in halves (128B data + 16B pad)

__device__ __align__(16) __half g_W[(size_t)OUT_F * IN_F];
__device__ __align__(16) __half g_X[(size_t)M_TOT * IN_F];

static __device__ __forceinline__ uint32_t smem_u32(const void* p) {
    return (uint32_t)__cvta_generic_to_shared(p);
}
static __device__ __forceinline__ void cp16(uint32_t dst, const void* src) {
    asm volatile("cp.async.cg.shared.global [%0], [%1], 16;\n" :: "r"(dst), "l"(src));
}
static __device__ __forceinline__ void ldsm4(uint32_t* d, uint32_t addr) {
    asm volatile("ldmatrix.sync.aligned.m8n8.x4.shared.b16 {%0,%1,%2,%3}, [%4];"
        : "=r"(d[0]), "=r"(d[1]), "=r"(d[2]), "=r"(d[3]) : "r"(addr));
}

// ---------------------------------------------------------------------------
// Fused prep: blocks [0, XBLK) do xscale, blocks [XBLK, XBLK+QBLK) do dequant.
// ---------------------------------------------------------------------------
#define XBLK ((M_TOT * IN_F / 8) / 256)              // 16384
#define QBLK ((OUT_F * (IN_F / 2) / 4) / 256)        // 5504

__global__ __launch_bounds__(256)
void prep_kernel(const float* __restrict__ x, const float* __restrict__ iscale,
                 const int* __restrict__ qw, const float* __restrict__ scales,
                 const float* __restrict__ zeros) {
    if (blockIdx.x < XBLK) {
        int idx = blockIdx.x * 256 + threadIdx.x;
        const float4* xp = (const float4*)x;
        float4 a = xp[2 * idx], b = xp[2 * idx + 1];
        int k4 = (2 * idx) & 1023;
        float4 sa = ((const float4*)iscale)[k4];
        float4 sb = ((const float4*)iscale)[k4 + 1];
        uint4 r;
        __half2 h;
        h = __floats2half2_rn(a.x * sa.x, a.y * sa.y); r.x = *reinterpret_cast<uint32_t*>(&h);
        h = __floats2half2_rn(a.z * sa.z, a.w * sa.w); r.y = *reinterpret_cast<uint32_t*>(&h);
        h = __floats2half2_rn(b.x * sb.x, b.y * sb.y); r.z = *reinterpret_cast<uint32_t*>(&h);
        h = __floats2half2_rn(b.z * sb.z, b.w * sb.w); r.w = *reinterpret_cast<uint32_t*>(&h);
        ((uint4*)g_X)[idx] = r;
    } else {
        int idx = (blockIdx.x - XBLK) * 256 + threadIdx.x;
        int4 v = ((const int4*)qw)[idx];
        int o  = idx >> 9;
        int jq = idx & 511;
        int g  = jq >> 4;
        float s  = scales[o * 32 + g];
        float zs = -zeros[o * 32 + g] * s;
        uint4 outv;
        __half2 h;
        h = __floats2half2_rn((float)((v.x >> 4) & 15) * s + zs, (float)(v.x & 15) * s + zs);
        outv.x = *reinterpret_cast<uint32_t*>(&h);
        h = __floats2half2_rn((float)((v.y >> 4) & 15) * s + zs, (float)(v.y & 15) * s + zs);
        outv.y = *reinterpret_cast<uint32_t*>(&h);
        h = __floats2half2_rn((float)((v.z >> 4) & 15) * s + zs, (float)(v.z & 15) * s + zs);
        outv.z = *reinterpret_cast<uint32_t*>(&h);
        h = __floats2half2_rn((float)((v.w >> 4) & 15) * s + zs, (float)(v.w & 15) * s + zs);
        outv.w = *reinterpret_cast<uint32_t*>(&h);
        ((uint4*)g_W)[(size_t)o * 512 + jq] = outv;
    }
}

// ---------------------------------------------------------------------------
// GEMM: BM=BN=128, 4 warps (2x2), 64x64 warp tile, BK=64, 3-stage cp.async,
// 2 CTAs/SM. Mid-iteration wait_group 1 gives the in-flight cp.async group
// ~1.5 iterations to complete instead of <1 (the R11 exposure).
// ---------------------------------------------------------------------------
__global__ __launch_bounds__(128, 2)
void gemm_kernel(const float* __restrict__ bias, float* __restrict__ C) {
    extern __shared__ __half smem[];
    __half* smA = smem;                         // NSTAGE * BM * ASTR
    __half* smB = smem + NSTAGE * BM * ASTR;    // NSTAGE * BN * ASTR

    const int tid  = threadIdx.x;
    const int lane = tid & 31;
    const int wid  = tid >> 5;
    const int wm   = wid & 1;    // 2 warp rows of 64
    const int wn   = wid >> 1;   // 2 warp cols of 64
    const int m0   = blockIdx.y * BM;
    const int n0   = blockIdx.x * BN;

    const char* gA = (const char*)(g_X + (size_t)m0 * IN_F);
    const char* gB = (const char*)(g_W + (size_t)n0 * IN_F);

    float acc[4][8][4];
    #pragma unroll
    for (int i = 0; i < 4; i++)
        #pragma unroll
        for (int j = 0; j < 8; j++)
            #pragma unroll
            for (int k = 0; k < 4; k++) acc[i][j][k] = 0.f;

    // lane-constant smem read offsets (bytes within a stage); kk adds 32B each
    uint32_t aoffs[4], boffs[4];
    #pragma unroll
    for (int mt = 0; mt < 4; mt++) {
        int row = wm * 64 + mt * 16 + (lane & 15);
        int col = (lane >> 4) * 8;
        aoffs[mt] = (uint32_t)(row * ASTR + col) * 2;
    }
    {
        int mi = lane >> 3, r = lane & 7;
        #pragma unroll
        for (int ntp = 0; ntp < 4; ntp++) {
            int n = wn * 64 + ntp * 16 + (mi >> 1) * 8 + r;
            int k = (mi & 1) * 8;
            boffs[ntp] = (uint32_t)(n * ASTR + k) * 2;
        }
    }

    // loader: per stage A=1024 chunks, B=1024 chunks over 128 threads (8+8 each)
    const int rA = tid >> 3, cA = tid & 7;
    auto issue = [&](int kt, int slot) {
        __half* sA = smA + slot * (BM * ASTR);
        __half* sB = smB + slot * (BN * ASTR);
        size_t koff = (size_t)kt * (BK * 2);   // byte offset in K
        #pragma unroll
        for (int i = 0; i < 8; i++) {
            int r = rA + i * 16;
            cp16(smem_u32(sA + r * ASTR + cA * 8),
                 gA + (size_t)r * (IN_F * 2) + koff + cA * 16);
            cp16(smem_u32(sB + r * ASTR + cA * 8),
                 gB + (size_t)r * (IN_F * 2) + koff + cA * 16);
        }
        asm volatile("cp.async.commit_group;\n");
    };

    uint32_t abuf[2][4][4];   // [buf][mt][frag]
    uint32_t bbuf[2][8][2];   // [buf][nt][frag]

    auto loadA = [&](uint32_t (*ab)[4], uint32_t base, uint32_t kkoff) {
        #pragma unroll
        for (int mt = 0; mt < 4; mt++) ldsm4(ab[mt], base + aoffs[mt] + kkoff);
    };
    auto loadB = [&](uint32_t (*bb)[2], uint32_t base, uint32_t kkoff) {
        #pragma unroll
        for (int ntp = 0; ntp < 4; ntp++) {
            uint32_t t[4];
            ldsm4(t, base + boffs[ntp] + kkoff);
            bb[2 * ntp][0] = t[0]; bb[2 * ntp][1] = t[1];
            bb[2 * ntp + 1][0] = t[2]; bb[2 * ntp + 1][1] = t[3];
        }
    };
    auto domma = [&](uint32_t (*ab)[4], uint32_t (*bb)[2]) {
        #pragma unroll
        for (int mt = 0; mt < 4; mt++)
            #pragma unroll
            for (int nt = 0; nt < 8; nt++) {
                asm volatile(
                    "mma.sync.aligned.m16n8k16.row.col.f32.f16.f16.f32 "
                    "{%0,%1,%2,%3}, {%4,%5,%6,%7}, {%8,%9}, {%0,%1,%2,%3};"
                    : "+f"(acc[mt][nt][0]), "+f"(acc[mt][nt][1]),
                      "+f"(acc[mt][nt][2]), "+f"(acc[mt][nt][3])
                    : "r"(ab[mt][0]), "r"(ab[mt][1]), "r"(ab[mt][2]), "r"(ab[mt][3]),
                      "r"(bb[nt][0]), "r"(bb[nt][1]));
            }
    };

    issue(0, 0); issue(1, 1);
    asm volatile("cp.async.wait_group 0;\n");   // slots 0 and 1 complete
    __syncthreads();

    // prime buf0 with (slot 0, kk0)
    loadA(abuf[0], smem_u32(smA), 0);
    loadB(bbuf[0], smem_u32(smB), 0);

    int cslot = 0;   // slot being consumed
    int islot = 2;   // slot to fill this iteration (kt+2)
    for (int kt = 0; kt < KT_CNT; kt++) {
        // invariant at top: buf0 = kk0 of slot kt (regs); slot kt complete;
        //                   all warps past reads of slot kt-1 (prev mid-sync)
        uint32_t ca = smem_u32(smA + cslot * (BM * ASTR));
        uint32_t cb = smem_u32(smB + cslot * (BN * ASTR));

        // kk1 LDSM first (ahead of the cp.async burst in the LSU queue)
        loadA(abuf[1], ca, 32);
        loadB(bbuf[1], cb, 32);

        if (kt + 2 < KT_CNT) issue(kt + 2, islot);
        else asm volatile("cp.async.commit_group;\n");  // keep group count uniform

        domma(abuf[0], bbuf[0]);           // kk0 (already in regs)

        loadA(abuf[0], ca, 64);
        loadB(bbuf[0], cb, 64);
        domma(abuf[1], bbuf[1]);           // kk1

        loadA(abuf[1], ca, 96);
        loadB(bbuf[1], cb, 96);
        domma(abuf[0], bbuf[0]);           // kk2

        // mid-iteration barrier: groups <= kt+1 complete (1 pending allowed),
        // and all warps finished reading slot kt (safe to rewrite next iter).
        asm volatile("cp.async.wait_group 1;\n");
        __syncthreads();

        // cross-tile prefetch: kk0 of slot kt+1 (complete per the wait)
        if (kt + 1 < KT_CNT) {
            int ns = (cslot + 1 == NSTAGE) ? 0 : cslot + 1;
            loadA(abuf[0], smem_u32(smA + ns * (BM * ASTR)), 0);
            loadB(bbuf[0], smem_u32(smB + ns * (BN * ASTR)), 0);
        }
        domma(abuf[1], bbuf[1]);           // kk3

        cslot = (cslot + 1 == NSTAGE) ? 0 : cslot + 1;
        islot = (islot + 1 == NSTAGE) ? 0 : islot + 1;
    }

    #pragma unroll
    for (int mt = 0; mt < 4; mt++) {
        int row = m0 + wm * 64 + mt * 16 + (lane >> 2);
        #pragma unroll
        for (int nt = 0; nt < 8; nt++) {
            int col = n0 + wn * 64 + nt * 8 + (lane & 3) * 2;
            float2 bv = *reinterpret_cast<const float2*>(bias + col);
            float2 v0 = make_float2(acc[mt][nt][0] + bv.x, acc[mt][nt][1] + bv.y);
            float2 v1 = make_float2(acc[mt][nt][2] + bv.x, acc[mt][nt][3] + bv.y);
            *reinterpret_cast<float2*>(C + (size_t)row * OUT_F + col)       = v0;
            *reinterpret_cast<float2*>(C + (size_t)(row + 8) * OUT_F + col) = v1;
        }
    }
}

// ---------------------------------------------------------------------------
extern "C" void kernel_launch(void* const* d_in, const int* in_sizes, int n_in,
                              void* d_out, int out_size) {
    const float* x      = (const float*)d_in[0];
    const int*   qw     = (const int*)  d_in[1];
    const float* scales = (const float*)d_in[2];
    const float* zeros  = (const float*)d_in[3];
    const float* iscale = (const float*)d_in[4];
    const float* bias   = (const float*)d_in[5];
    float* out = (float*)d_out;

    prep_kernel<<<XBLK + QBLK, 256>>>(x, iscale, qw, scales, zeros);

    constexpr int SMEM_BYTES = NSTAGE * (BM + BN) * ASTR * 2;   // 110592
    cudaFuncSetAttribute(gemm_kernel, cudaFuncAttributeMaxDynamicSharedMemorySize, SMEM_BYTES);
    dim3 grid(OUT_F / BN, M_TOT / BM);   // 86 x 64
    gemm_kernel<<<grid, 128, SMEM_BYTES>>>(bias, out);
}